// round 1
// baseline (speedup 1.0000x reference)
#include <cuda_runtime.h>
#include <cuda_bf16.h>

// Problem constants
#define CTXD   512
#define HIDD   2048
#define NCELLS 4096      // 64*64
#define NBATCH 8
#define KNN    8
#define MTOT   (NBATCH * NCELLS)   // 32768

// 64 MB scratch for the aggregated context (allowed: __device__ global)
__device__ float g_agg[(size_t)MTOT * CTXD];

// ---------------------------------------------------------------------------
// Kernel 1: agg[b,n,c] = sum_k sim[n,k] * x[b, nn_idx[n,k], c]
// grid = (NCELLS, NBATCH), block = 128 threads, one float4 per thread (CTX/4)
// ---------------------------------------------------------------------------
__global__ __launch_bounds__(128) void agg_kernel(
    const float* __restrict__ x,      // (B, N, CTX)
    const int*   __restrict__ nn_idx, // (N, K)
    const float* __restrict__ sim)    // (N, K)
{
    const int n = blockIdx.x;
    const int b = blockIdx.y;
    const int t = threadIdx.x;        // 0..127 -> float4 lane

    __shared__ int   s_idx[KNN];
    __shared__ float s_sim[KNN];
    if (t < KNN) {
        s_idx[t] = nn_idx[n * KNN + t];
        s_sim[t] = sim[n * KNN + t];
    }
    __syncthreads();

    const float4* xb = reinterpret_cast<const float4*>(x) +
                       (size_t)b * NCELLS * (CTXD / 4);

    float4 acc = make_float4(0.f, 0.f, 0.f, 0.f);
#pragma unroll
    for (int k = 0; k < KNN; k++) {
        const float  s = s_sim[k];
        const float4 v = xb[(size_t)s_idx[k] * (CTXD / 4) + t];
        acc.x = fmaf(s, v.x, acc.x);
        acc.y = fmaf(s, v.y, acc.y);
        acc.z = fmaf(s, v.z, acc.z);
        acc.w = fmaf(s, v.w, acc.w);
    }
    reinterpret_cast<float4*>(g_agg)[((size_t)b * NCELLS + n) * (CTXD / 4) + t] = acc;
}

// ---------------------------------------------------------------------------
// Kernel 2: C = A @ W,  A = g_agg (MTOT x CTX), W (CTX x HID), C (MTOT x HID)
// 128x128 block tile, BK=8, 256 threads, 8x8 per-thread, double-buffered smem
// ---------------------------------------------------------------------------
#define BM 128
#define BN 128
#define BK 8

__global__ __launch_bounds__(256) void gemm_kernel(
    const float* __restrict__ A,   // MTOT x CTXD
    const float* __restrict__ W,   // CTXD x HIDD
    float*       __restrict__ C)   // MTOT x HIDD
{
    __shared__ float As[2][BK][BM];   // stored transposed: As[k][m]
    __shared__ float Bs[2][BK][BN];

    const int tid = threadIdx.x;
    const int tx  = tid & 15;         // 0..15  (N direction)
    const int ty  = tid >> 4;         // 0..15  (M direction)

    const int m0 = blockIdx.y * BM;
    const int n0 = blockIdx.x * BN;

    // A-tile load mapping: 256 threads x 1 float4 = 128 rows x 8 cols
    const int aRow = tid >> 1;            // 0..127
    const int aCol = (tid & 1) * 4;       // 0 or 4
    // B-tile load mapping: 8 rows x 128 cols
    const int bRow = tid >> 5;            // 0..7
    const int bCol = (tid & 31) * 4;      // 0..124

    const int nTiles = CTXD / BK;         // 64

    // --- preload tile 0 ---
    {
        float4 av = *reinterpret_cast<const float4*>(
            &A[(size_t)(m0 + aRow) * CTXD + aCol]);
        As[0][aCol + 0][aRow] = av.x;
        As[0][aCol + 1][aRow] = av.y;
        As[0][aCol + 2][aRow] = av.z;
        As[0][aCol + 3][aRow] = av.w;
        float4 bv = *reinterpret_cast<const float4*>(
            &W[(size_t)bRow * HIDD + n0 + bCol]);
        *reinterpret_cast<float4*>(&Bs[0][bRow][bCol]) = bv;
    }
    __syncthreads();

    float acc[8][8];
#pragma unroll
    for (int i = 0; i < 8; i++)
#pragma unroll
        for (int j = 0; j < 8; j++) acc[i][j] = 0.f;

    for (int t = 0; t < nTiles; t++) {
        const int cur = t & 1;
        const int nxt = cur ^ 1;

        float4 av, bv;
        const bool hasNext = (t + 1) < nTiles;
        if (hasNext) {
            const int k0 = (t + 1) * BK;
            av = *reinterpret_cast<const float4*>(
                &A[(size_t)(m0 + aRow) * CTXD + k0 + aCol]);
            bv = *reinterpret_cast<const float4*>(
                &W[(size_t)(k0 + bRow) * HIDD + n0 + bCol]);
        }

#pragma unroll
        for (int kk = 0; kk < BK; kk++) {
            float aFrag[8], bFrag[8];
            float4 a0 = *reinterpret_cast<const float4*>(&As[cur][kk][ty * 4]);
            float4 a1 = *reinterpret_cast<const float4*>(&As[cur][kk][64 + ty * 4]);
            float4 b0 = *reinterpret_cast<const float4*>(&Bs[cur][kk][tx * 4]);
            float4 b1 = *reinterpret_cast<const float4*>(&Bs[cur][kk][64 + tx * 4]);
            aFrag[0]=a0.x; aFrag[1]=a0.y; aFrag[2]=a0.z; aFrag[3]=a0.w;
            aFrag[4]=a1.x; aFrag[5]=a1.y; aFrag[6]=a1.z; aFrag[7]=a1.w;
            bFrag[0]=b0.x; bFrag[1]=b0.y; bFrag[2]=b0.z; bFrag[3]=b0.w;
            bFrag[4]=b1.x; bFrag[5]=b1.y; bFrag[6]=b1.z; bFrag[7]=b1.w;
#pragma unroll
            for (int i = 0; i < 8; i++)
#pragma unroll
                for (int j = 0; j < 8; j++)
                    acc[i][j] = fmaf(aFrag[i], bFrag[j], acc[i][j]);
        }

        if (hasNext) {
            As[nxt][aCol + 0][aRow] = av.x;
            As[nxt][aCol + 1][aRow] = av.y;
            As[nxt][aCol + 2][aRow] = av.z;
            As[nxt][aCol + 3][aRow] = av.w;
            *reinterpret_cast<float4*>(&Bs[nxt][bRow][bCol]) = bv;
        }
        __syncthreads();
    }

    // --- epilogue: two row groups x two col groups, float4 stores ---
#pragma unroll
    for (int rg = 0; rg < 2; rg++) {
#pragma unroll
        for (int i = 0; i < 4; i++) {
            const int row = m0 + rg * 64 + ty * 4 + i;
            float* crow = C + (size_t)row * HIDD + n0;
            float4 v0, v1;
            v0.x = acc[rg * 4 + i][0]; v0.y = acc[rg * 4 + i][1];
            v0.z = acc[rg * 4 + i][2]; v0.w = acc[rg * 4 + i][3];
            v1.x = acc[rg * 4 + i][4]; v1.y = acc[rg * 4 + i][5];
            v1.z = acc[rg * 4 + i][6]; v1.w = acc[rg * 4 + i][7];
            *reinterpret_cast<float4*>(&crow[tx * 4])      = v0;
            *reinterpret_cast<float4*>(&crow[64 + tx * 4]) = v1;
        }
    }
}

// ---------------------------------------------------------------------------
extern "C" void kernel_launch(void* const* d_in, const int* in_sizes, int n_in,
                              void* d_out, int out_size) {
    const float* x      = (const float*)d_in[0];  // (8, 64, 64, 512)
    const float* W      = (const float*)d_in[1];  // (512, 2048)
    const int*   nn_idx = (const int*)  d_in[2];  // (4096, 8)
    const float* sim    = (const float*)d_in[3];  // (4096, 8)
    float*       out    = (float*)d_out;          // (8, 64, 64, 2048)

    float* agg = nullptr;
    cudaGetSymbolAddress((void**)&agg, g_agg);

    dim3 g1(NCELLS, NBATCH);
    agg_kernel<<<g1, 128>>>(x, nn_idx, sim);

    dim3 g2(HIDD / BN, MTOT / BM);
    gemm_kernel<<<g2, 256>>>(agg, W, out);
}

// round 2
// speedup vs baseline: 2.7574x; 2.7574x over previous
#include <cuda_runtime.h>
#include <cuda_bf16.h>
#include <cstdint>

// Problem constants
#define CTXD   512
#define HIDD   2048
#define NCELLS 4096      // 64*64
#define NBATCH 8
#define KNN    8
#define MTOT   (NBATCH * NCELLS)   // 32768

// Scratch (allowed: __device__ globals)
__device__ float g_agg[(size_t)MTOT * CTXD];   // 64 MB, tf32-rounded agg
__device__ float g_Wt[(size_t)CTXD * HIDD];    // 4 MB, tf32-rounded W

__device__ __forceinline__ float to_tf32(float x) {
    uint32_t u;
    asm("cvt.rna.tf32.f32 %0, %1;" : "=r"(u) : "f"(x));
    return __uint_as_float(u);
}

// ---------------------------------------------------------------------------
// Kernel 1: agg[b,n,c] = sum_k sim[n,k] * x[b, nn_idx[n,k], c]  (tf32-rounded)
// ---------------------------------------------------------------------------
__global__ __launch_bounds__(128) void agg_kernel(
    const float* __restrict__ x,      // (B, N, CTX)
    const int*   __restrict__ nn_idx, // (N, K)
    const float* __restrict__ sim)    // (N, K)
{
    const int n = blockIdx.x;
    const int b = blockIdx.y;
    const int t = threadIdx.x;

    __shared__ int   s_idx[KNN];
    __shared__ float s_sim[KNN];
    if (t < KNN) {
        s_idx[t] = nn_idx[n * KNN + t];
        s_sim[t] = sim[n * KNN + t];
    }
    __syncthreads();

    const float4* xb = reinterpret_cast<const float4*>(x) +
                       (size_t)b * NCELLS * (CTXD / 4);

    float4 acc = make_float4(0.f, 0.f, 0.f, 0.f);
#pragma unroll
    for (int k = 0; k < KNN; k++) {
        const float  s = s_sim[k];
        const float4 v = xb[(size_t)s_idx[k] * (CTXD / 4) + t];
        acc.x = fmaf(s, v.x, acc.x);
        acc.y = fmaf(s, v.y, acc.y);
        acc.z = fmaf(s, v.z, acc.z);
        acc.w = fmaf(s, v.w, acc.w);
    }
    acc.x = to_tf32(acc.x); acc.y = to_tf32(acc.y);
    acc.z = to_tf32(acc.z); acc.w = to_tf32(acc.w);
    reinterpret_cast<float4*>(g_agg)[((size_t)b * NCELLS + n) * (CTXD / 4) + t] = acc;
}

// ---------------------------------------------------------------------------
// Kernel 1b: round W to tf32 once per launch
// ---------------------------------------------------------------------------
__global__ __launch_bounds__(256) void wconv_kernel(
    const float* __restrict__ W, float* __restrict__ o)
{
    const int i = blockIdx.x * 256 + threadIdx.x;   // float4 index
    float4 v = reinterpret_cast<const float4*>(W)[i];
    v.x = to_tf32(v.x); v.y = to_tf32(v.y);
    v.z = to_tf32(v.z); v.w = to_tf32(v.w);
    reinterpret_cast<float4*>(o)[i] = v;
}

// ---------------------------------------------------------------------------
// Kernel 2: TF32 tensor-core GEMM  C = A @ B
// A: MTOT x CTXD (tf32 values in fp32), B: CTXD x HIDD, C: MTOT x HIDD
// Block tile 128x128, BK=32, 256 threads (8 warps, warp tile 64x32),
// cp.async double-buffered smem, mma.sync.m16n8k8.tf32.
// ---------------------------------------------------------------------------
#define BM 128
#define BN 128
#define BK 32
#define ASTRIDE 36     // 32 + 4 pad  -> conflict-free A-frag LDS
#define BSTRIDE 132    // 128 + 4 pad -> conflict-free B-frag LDS
#define NKTILES (CTXD / BK)   // 16
#define GEMM_SMEM_BYTES ((2 * BM * ASTRIDE + 2 * BK * BSTRIDE) * 4)  // 70656

__device__ __forceinline__ void cpasync16(uint32_t saddr, const void* g) {
    asm volatile("cp.async.cg.shared.global [%0], [%1], 16;\n"
                 :: "r"(saddr), "l"(g));
}

__global__ __launch_bounds__(256, 2) void gemm_tf32(
    const float* __restrict__ A,
    const float* __restrict__ B,
    float*       __restrict__ C)
{
    extern __shared__ float sm[];
    float* As = sm;                        // [2][BM][ASTRIDE]
    float* Bs = sm + 2 * BM * ASTRIDE;     // [2][BK][BSTRIDE]

    const int tid  = threadIdx.x;
    const int lane = tid & 31;
    const int warp = tid >> 5;
    const int wm   = warp & 1;     // 0..1 : M sub-tile of 64
    const int wn   = warp >> 1;    // 0..3 : N sub-tile of 32
    const int m0   = blockIdx.y * BM;
    const int n0   = blockIdx.x * BN;

    const int lg  = lane >> 2;     // 0..7
    const int lt  = lane & 3;      // 0..3

    float acc[4][4][4];
#pragma unroll
    for (int i = 0; i < 4; i++)
#pragma unroll
        for (int j = 0; j < 4; j++)
#pragma unroll
            for (int r = 0; r < 4; r++) acc[i][j][r] = 0.f;

    // tile loader (cp.async, one commit group per tile)
    auto load_tile = [&](int buf, int kt) {
        const float* Ag = A + (size_t)m0 * CTXD + kt * BK;
        const float* Bg = B + (size_t)(kt * BK) * HIDD + n0;
        float* Asb = As + buf * BM * ASTRIDE;
        float* Bsb = Bs + buf * BK * BSTRIDE;
#pragma unroll
        for (int i = 0; i < 4; i++) {
            int c  = i * 256 + tid;
            int r  = c >> 3;                // 0..127
            int k4 = (c & 7) << 2;          // 0..28
            cpasync16((uint32_t)__cvta_generic_to_shared(Asb + r * ASTRIDE + k4),
                      Ag + (size_t)r * CTXD + k4);
        }
#pragma unroll
        for (int i = 0; i < 4; i++) {
            int c  = i * 256 + tid;
            int r  = c >> 5;                // 0..31
            int n4 = (c & 31) << 2;         // 0..124
            cpasync16((uint32_t)__cvta_generic_to_shared(Bsb + r * BSTRIDE + n4),
                      Bg + (size_t)r * HIDD + n4);
        }
        asm volatile("cp.async.commit_group;\n");
    };

    load_tile(0, 0);

    for (int kt = 0; kt < NKTILES; ++kt) {
        const int cur = kt & 1;
        if (kt + 1 < NKTILES) {
            load_tile(cur ^ 1, kt + 1);
            asm volatile("cp.async.wait_group 1;\n");
        } else {
            asm volatile("cp.async.wait_group 0;\n");
        }
        __syncthreads();

        const float* Asb = As + cur * BM * ASTRIDE;
        const float* Bsb = Bs + cur * BK * BSTRIDE;

#pragma unroll
        for (int ks = 0; ks < 4; ++ks) {
            const int k0 = ks * 8;

            uint32_t af[4][4];
#pragma unroll
            for (int mi = 0; mi < 4; ++mi) {
                const float* p = Asb + (wm * 64 + mi * 16 + lg) * ASTRIDE + k0 + lt;
                af[mi][0] = __float_as_uint(p[0]);
                af[mi][1] = __float_as_uint(p[8 * ASTRIDE]);
                af[mi][2] = __float_as_uint(p[4]);
                af[mi][3] = __float_as_uint(p[8 * ASTRIDE + 4]);
            }
            uint32_t bf[4][2];
#pragma unroll
            for (int ni = 0; ni < 4; ++ni) {
                const float* p = Bsb + (k0 + lt) * BSTRIDE + wn * 32 + ni * 8 + lg;
                bf[ni][0] = __float_as_uint(p[0]);
                bf[ni][1] = __float_as_uint(p[4 * BSTRIDE]);
            }
#pragma unroll
            for (int mi = 0; mi < 4; ++mi)
#pragma unroll
                for (int ni = 0; ni < 4; ++ni) {
                    asm volatile(
                        "mma.sync.aligned.m16n8k8.row.col.f32.tf32.tf32.f32 "
                        "{%0,%1,%2,%3},{%4,%5,%6,%7},{%8,%9},{%0,%1,%2,%3};\n"
                        : "+f"(acc[mi][ni][0]), "+f"(acc[mi][ni][1]),
                          "+f"(acc[mi][ni][2]), "+f"(acc[mi][ni][3])
                        : "r"(af[mi][0]), "r"(af[mi][1]),
                          "r"(af[mi][2]), "r"(af[mi][3]),
                          "r"(bf[ni][0]), "r"(bf[ni][1]));
                }
        }
        __syncthreads();
    }

    // epilogue: float2 stores, 32B-coalesced per 4-lane group
#pragma unroll
    for (int mi = 0; mi < 4; ++mi) {
#pragma unroll
        for (int ni = 0; ni < 4; ++ni) {
            const int r = m0 + wm * 64 + mi * 16 + lg;
            const int c = n0 + wn * 32 + ni * 8 + (lt << 1);
            float2 v0 = make_float2(acc[mi][ni][0], acc[mi][ni][1]);
            float2 v1 = make_float2(acc[mi][ni][2], acc[mi][ni][3]);
            *reinterpret_cast<float2*>(C + (size_t)r * HIDD + c)       = v0;
            *reinterpret_cast<float2*>(C + (size_t)(r + 8) * HIDD + c) = v1;
        }
    }
}

// ---------------------------------------------------------------------------
extern "C" void kernel_launch(void* const* d_in, const int* in_sizes, int n_in,
                              void* d_out, int out_size) {
    const float* x      = (const float*)d_in[0];  // (8, 64, 64, 512)
    const float* W      = (const float*)d_in[1];  // (512, 2048)
    const int*   nn_idx = (const int*)  d_in[2];  // (4096, 8)
    const float* sim    = (const float*)d_in[3];  // (4096, 8)
    float*       out    = (float*)d_out;          // (8, 64, 64, 2048)

    float* agg = nullptr;
    float* wt  = nullptr;
    cudaGetSymbolAddress((void**)&agg, g_agg);
    cudaGetSymbolAddress((void**)&wt,  g_Wt);

    cudaFuncSetAttribute(gemm_tf32,
                         cudaFuncAttributeMaxDynamicSharedMemorySize,
                         GEMM_SMEM_BYTES);

    dim3 g1(NCELLS, NBATCH);
    agg_kernel<<<g1, 128>>>(x, nn_idx, sim);

    wconv_kernel<<<(CTXD * HIDD / 4) / 256, 256>>>(W, wt);

    dim3 g2(HIDD / BN, MTOT / BM);
    gemm_tf32<<<g2, 256, GEMM_SMEM_BYTES>>>(agg, wt, out);
}

// round 4
// speedup vs baseline: 4.4070x; 1.5983x over previous
#include <cuda_runtime.h>
#include <cuda_fp16.h>
#include <cstdint>

// Problem constants
#define CTXD   512
#define HIDD   2048
#define NCELLS 4096      // 64*64
#define NBATCH 8
#define KNN    8
#define MTOT   (NBATCH * NCELLS)   // 32768

// Scratch (allowed: __device__ globals)
__device__ __half g_aggh[(size_t)MTOT * CTXD];  // 32 MB fp16 agg
__device__ __half g_Wh[(size_t)HIDD * CTXD];    // 2 MB  fp16 W^T (N rows, K cols)

// ---------------------------------------------------------------------------
// Kernel 1: agg[b,n,c] = sum_k sim[n,k]*x[b,nn[n,k],c]   -> fp16
// ---------------------------------------------------------------------------
__global__ __launch_bounds__(128) void agg_kernel(
    const float* __restrict__ x,
    const int*   __restrict__ nn_idx,
    const float* __restrict__ sim)
{
    const int n = blockIdx.x;
    const int b = blockIdx.y;
    const int t = threadIdx.x;

    __shared__ int   s_idx[KNN];
    __shared__ float s_sim[KNN];
    if (t < KNN) {
        s_idx[t] = nn_idx[n * KNN + t];
        s_sim[t] = sim[n * KNN + t];
    }
    __syncthreads();

    const float4* xb = reinterpret_cast<const float4*>(x) +
                       (size_t)b * NCELLS * (CTXD / 4);

    float4 acc = make_float4(0.f, 0.f, 0.f, 0.f);
#pragma unroll
    for (int k = 0; k < KNN; k++) {
        const float  s = s_sim[k];
        const float4 v = xb[(size_t)s_idx[k] * (CTXD / 4) + t];
        acc.x = fmaf(s, v.x, acc.x);
        acc.y = fmaf(s, v.y, acc.y);
        acc.z = fmaf(s, v.z, acc.z);
        acc.w = fmaf(s, v.w, acc.w);
    }
    __half2 h0 = __float22half2_rn(make_float2(acc.x, acc.y));
    __half2 h1 = __float22half2_rn(make_float2(acc.z, acc.w));
    uint2 pack;
    pack.x = *reinterpret_cast<uint32_t*>(&h0);
    pack.y = *reinterpret_cast<uint32_t*>(&h1);
    reinterpret_cast<uint2*>(g_aggh)[((size_t)b * NCELLS + n) * (CTXD / 4) + t] = pack;
}

// ---------------------------------------------------------------------------
// Kernel 1b: Wt[n][k] = (half)W[k][n]   (2048 x 512 fp16, K-major rows)
// ---------------------------------------------------------------------------
__global__ __launch_bounds__(256) void wtrans_kernel(
    const float* __restrict__ W, __half* __restrict__ o)
{
    __shared__ float tile[32][33];
    const int bx = blockIdx.x;   // n block
    const int by = blockIdx.y;   // k block
    const int tx = threadIdx.x & 31;
    const int ty = threadIdx.x >> 5;   // 0..7
#pragma unroll
    for (int i = 0; i < 4; i++)
        tile[ty + i * 8][tx] = W[(size_t)(by * 32 + ty + i * 8) * HIDD + bx * 32 + tx];
    __syncthreads();
#pragma unroll
    for (int i = 0; i < 4; i++)
        o[(size_t)(bx * 32 + ty + i * 8) * CTXD + by * 32 + tx] =
            __float2half(tile[tx][ty + i * 8]);
}

// ---------------------------------------------------------------------------
// Kernel 2: fp16 mma.sync GEMM  C[M,N] = A[M,K] @ Wt[N,K]^T, fp32 accum
// 128x128 tile, BK=32, 3-stage cp.async, 256 thr (8 warps, warp 64x32)
// ---------------------------------------------------------------------------
#define BM 128
#define BN 128
#define BK 32
#define NT (CTXD / BK)         // 16 k-chunks
#define SSTRIDE 40             // BK + 8 pad (halves) -> conflict-free
#define TILE_H (128 * SSTRIDE) // halves per tile (A or B)
#define STAGE_H (2 * TILE_H)   // A then B
#define GEMM_SMEM (3 * STAGE_H * 2)   // bytes = 61440

__device__ __forceinline__ void cpasync16(uint32_t saddr, const void* g) {
    asm volatile("cp.async.cg.shared.global [%0], [%1], 16;\n" :: "r"(saddr), "l"(g));
}

__global__ __launch_bounds__(256, 2) void gemm_hmma(
    const __half* __restrict__ A,   // [MTOT][CTXD]
    const __half* __restrict__ B,   // [HIDD][CTXD]  (W^T)
    float*        __restrict__ C)   // [MTOT][HIDD]
{
    extern __shared__ __half sm[];

    const int tid  = threadIdx.x;
    const int lane = tid & 31;
    const int warp = tid >> 5;
    const int wm   = warp & 1;     // 0..1 : 64-row M sub-tile
    const int wn   = warp >> 1;    // 0..3 : 32-col N sub-tile
    const int g    = lane >> 2;    // 0..7
    const int t4   = lane & 3;     // 0..3

    const int m0 = blockIdx.y * BM;
    const int n0 = blockIdx.x * BN;

    float acc[4][4][4];
#pragma unroll
    for (int i = 0; i < 4; i++)
#pragma unroll
        for (int j = 0; j < 4; j++)
#pragma unroll
            for (int r = 0; r < 4; r++) acc[i][j][r] = 0.f;

    // loader: chunk kt -> stage buf (A: 128x32, B: 128x32, 16B = 8 halves)
    auto load_chunk = [&](int buf, int kt) {
        __half* Asb = sm + buf * STAGE_H;
        __half* Bsb = Asb + TILE_H;
        const __half* Ag = A + (size_t)m0 * CTXD + kt * BK;
        const __half* Bg = B + (size_t)n0 * CTXD + kt * BK;
#pragma unroll
        for (int i = 0; i < 2; i++) {
            int idx = i * 256 + tid;
            int row = idx >> 2;
            int c8  = (idx & 3) * 8;
            cpasync16((uint32_t)__cvta_generic_to_shared(Asb + row * SSTRIDE + c8),
                      Ag + (size_t)row * CTXD + c8);
        }
#pragma unroll
        for (int i = 0; i < 2; i++) {
            int idx = i * 256 + tid;
            int row = idx >> 2;
            int c8  = (idx & 3) * 8;
            cpasync16((uint32_t)__cvta_generic_to_shared(Bsb + row * SSTRIDE + c8),
                      Bg + (size_t)row * CTXD + c8);
        }
        asm volatile("cp.async.commit_group;\n");
    };

    load_chunk(0, 0);
    load_chunk(1, 1);

    for (int kt = 0; kt < NT; ++kt) {
        if (kt + 2 < NT) {
            load_chunk((kt + 2) % 3, kt + 2);
            asm volatile("cp.async.wait_group 2;\n");
        } else if (kt + 1 < NT) {
            asm volatile("cp.async.wait_group 1;\n");
        } else {
            asm volatile("cp.async.wait_group 0;\n");
        }
        __syncthreads();

        const __half* Asb = sm + (kt % 3) * STAGE_H;
        const __half* Bsb = Asb + TILE_H;

#pragma unroll
        for (int ks = 0; ks < 2; ++ks) {
            const int k0 = ks * 16;

            uint32_t af[4][4];
#pragma unroll
            for (int mi = 0; mi < 4; ++mi) {
                const __half* p = Asb + (wm * 64 + mi * 16 + g) * SSTRIDE + k0 + t4 * 2;
                af[mi][0] = *reinterpret_cast<const uint32_t*>(p);
                af[mi][1] = *reinterpret_cast<const uint32_t*>(p + 8 * SSTRIDE);
                af[mi][2] = *reinterpret_cast<const uint32_t*>(p + 8);
                af[mi][3] = *reinterpret_cast<const uint32_t*>(p + 8 * SSTRIDE + 8);
            }
            uint32_t bf[4][2];
#pragma unroll
            for (int ni = 0; ni < 4; ++ni) {
                const __half* p = Bsb + (wn * 32 + ni * 8 + g) * SSTRIDE + k0 + t4 * 2;
                bf[ni][0] = *reinterpret_cast<const uint32_t*>(p);
                bf[ni][1] = *reinterpret_cast<const uint32_t*>(p + 8);
            }
#pragma unroll
            for (int mi = 0; mi < 4; ++mi)
#pragma unroll
                for (int ni = 0; ni < 4; ++ni) {
                    asm volatile(
                        "mma.sync.aligned.m16n8k16.row.col.f32.f16.f16.f32 "
                        "{%0,%1,%2,%3},{%4,%5,%6,%7},{%8,%9},{%0,%1,%2,%3};\n"
                        : "+f"(acc[mi][ni][0]), "+f"(acc[mi][ni][1]),
                          "+f"(acc[mi][ni][2]), "+f"(acc[mi][ni][3])
                        : "r"(af[mi][0]), "r"(af[mi][1]),
                          "r"(af[mi][2]), "r"(af[mi][3]),
                          "r"(bf[ni][0]), "r"(bf[ni][1]));
                }
        }
        __syncthreads();
    }

    // epilogue: float2 stores (d0,d1 at row g; d2,d3 at row g+8)
#pragma unroll
    for (int mi = 0; mi < 4; ++mi) {
#pragma unroll
        for (int ni = 0; ni < 4; ++ni) {
            const int r = m0 + wm * 64 + mi * 16 + g;
            const int c = n0 + wn * 32 + ni * 8 + t4 * 2;
            float2 v0 = make_float2(acc[mi][ni][0], acc[mi][ni][1]);
            float2 v1 = make_float2(acc[mi][ni][2], acc[mi][ni][3]);
            *reinterpret_cast<float2*>(C + (size_t)r * HIDD + c)       = v0;
            *reinterpret_cast<float2*>(C + (size_t)(r + 8) * HIDD + c) = v1;
        }
    }
}

// ---------------------------------------------------------------------------
extern "C" void kernel_launch(void* const* d_in, const int* in_sizes, int n_in,
                              void* d_out, int out_size) {
    const float* x      = (const float*)d_in[0];
    const float* W      = (const float*)d_in[1];
    const int*   nn_idx = (const int*)  d_in[2];
    const float* sim    = (const float*)d_in[3];
    float*       out    = (float*)d_out;

    __half* aggh = nullptr;
    __half* wh   = nullptr;
    cudaGetSymbolAddress((void**)&aggh, g_aggh);
    cudaGetSymbolAddress((void**)&wh,   g_Wh);

    cudaFuncSetAttribute(gemm_hmma,
                         cudaFuncAttributeMaxDynamicSharedMemorySize, GEMM_SMEM);

    dim3 g1(NCELLS, NBATCH);
    agg_kernel<<<g1, 128>>>(x, nn_idx, sim);

    dim3 gt(HIDD / 32, CTXD / 32);
    wtrans_kernel<<<gt, 256>>>(W, wh);

    dim3 g2(HIDD / BN, MTOT / BM);   // (16, 256)
    gemm_hmma<<<g2, 256, GEMM_SMEM>>>(aggh, wh, out);
}

// round 5
// speedup vs baseline: 4.6031x; 1.0445x over previous
#include <cuda_runtime.h>
#include <cuda_fp16.h>
#include <cstdint>

// Problem constants
#define CTXD   512
#define HIDD   2048
#define NCELLS 4096      // 64*64
#define NBATCH 8
#define KNN    8
#define MTOT   (NBATCH * NCELLS)   // 32768

// Scratch (allowed: __device__ globals)
__device__ __half g_aggh[(size_t)MTOT * CTXD];  // 32 MB fp16 agg
__device__ __half g_Wh[(size_t)HIDD * CTXD];    // 2 MB  fp16 W^T (N rows, K cols)

// ---------------------------------------------------------------------------
// Kernel 1: agg -> fp16, two cells per block for ILP
// ---------------------------------------------------------------------------
__global__ __launch_bounds__(128) void agg_kernel(
    const float* __restrict__ x,
    const int*   __restrict__ nn_idx,
    const float* __restrict__ sim)
{
    const int n0 = blockIdx.x * 2;     // cells n0, n0+1
    const int b  = blockIdx.y;
    const int t  = threadIdx.x;

    __shared__ int   s_idx[2 * KNN];
    __shared__ float s_sim[2 * KNN];
    if (t < 2 * KNN) {
        s_idx[t] = nn_idx[n0 * KNN + t];
        s_sim[t] = sim[n0 * KNN + t];
    }
    __syncthreads();

    const float4* xb = reinterpret_cast<const float4*>(x) +
                       (size_t)b * NCELLS * (CTXD / 4);

    float4 acc0 = make_float4(0.f, 0.f, 0.f, 0.f);
    float4 acc1 = make_float4(0.f, 0.f, 0.f, 0.f);
#pragma unroll
    for (int k = 0; k < KNN; k++) {
        const float  sa = s_sim[k];
        const float  sb = s_sim[KNN + k];
        const float4 va = xb[(size_t)s_idx[k] * (CTXD / 4) + t];
        const float4 vb = xb[(size_t)s_idx[KNN + k] * (CTXD / 4) + t];
        acc0.x = fmaf(sa, va.x, acc0.x); acc0.y = fmaf(sa, va.y, acc0.y);
        acc0.z = fmaf(sa, va.z, acc0.z); acc0.w = fmaf(sa, va.w, acc0.w);
        acc1.x = fmaf(sb, vb.x, acc1.x); acc1.y = fmaf(sb, vb.y, acc1.y);
        acc1.z = fmaf(sb, vb.z, acc1.z); acc1.w = fmaf(sb, vb.w, acc1.w);
    }
    __half2 a0 = __float22half2_rn(make_float2(acc0.x, acc0.y));
    __half2 a1 = __float22half2_rn(make_float2(acc0.z, acc0.w));
    __half2 b0 = __float22half2_rn(make_float2(acc1.x, acc1.y));
    __half2 b1 = __float22half2_rn(make_float2(acc1.z, acc1.w));
    uint2 p0, p1;
    p0.x = *reinterpret_cast<uint32_t*>(&a0);
    p0.y = *reinterpret_cast<uint32_t*>(&a1);
    p1.x = *reinterpret_cast<uint32_t*>(&b0);
    p1.y = *reinterpret_cast<uint32_t*>(&b1);
    uint2* dst = reinterpret_cast<uint2*>(g_aggh);
    dst[((size_t)b * NCELLS + n0)     * (CTXD / 4) + t] = p0;
    dst[((size_t)b * NCELLS + n0 + 1) * (CTXD / 4) + t] = p1;
}

// ---------------------------------------------------------------------------
// Kernel 1b: Wt[n][k] = (half)W[k][n]
// ---------------------------------------------------------------------------
__global__ __launch_bounds__(256) void wtrans_kernel(
    const float* __restrict__ W, __half* __restrict__ o)
{
    __shared__ float tile[32][33];
    const int bx = blockIdx.x;
    const int by = blockIdx.y;
    const int tx = threadIdx.x & 31;
    const int ty = threadIdx.x >> 5;
#pragma unroll
    for (int i = 0; i < 4; i++)
        tile[ty + i * 8][tx] = W[(size_t)(by * 32 + ty + i * 8) * HIDD + bx * 32 + tx];
    __syncthreads();
#pragma unroll
    for (int i = 0; i < 4; i++)
        o[(size_t)(bx * 32 + ty + i * 8) * CTXD + by * 32 + tx] =
            __float2half(tile[tx][ty + i * 8]);
}

// ---------------------------------------------------------------------------
// Kernel 2: fp16 mma.sync GEMM, 128x128 CTA tile, 4 warps (warp tile 64x64),
// BK=32, 3-stage cp.async, fp32 accum.
// ---------------------------------------------------------------------------
#define BM 128
#define BN 128
#define BK 32
#define NT (CTXD / BK)         // 16 k-chunks
#define SSTRIDE 40             // BK + 8 pad (halves)
#define TILE_H (128 * SSTRIDE)
#define STAGE_H (2 * TILE_H)
#define GEMM_SMEM (3 * STAGE_H * 2)   // 61440 bytes

__device__ __forceinline__ void cpasync16(uint32_t saddr, const void* g) {
    asm volatile("cp.async.cg.shared.global [%0], [%1], 16;\n" :: "r"(saddr), "l"(g));
}

__global__ __launch_bounds__(128, 2) void gemm_hmma(
    const __half* __restrict__ A,   // [MTOT][CTXD]
    const __half* __restrict__ B,   // [HIDD][CTXD]  (W^T)
    float*        __restrict__ C)   // [MTOT][HIDD]
{
    extern __shared__ __half sm[];

    const int tid  = threadIdx.x;
    const int lane = tid & 31;
    const int warp = tid >> 5;      // 0..3
    const int wm   = warp & 1;      // 64-row M half
    const int wn   = warp >> 1;     // 64-col N half
    const int g    = lane >> 2;     // 0..7
    const int t4   = lane & 3;      // 0..3

    const int m0 = blockIdx.y * BM;
    const int n0 = blockIdx.x * BN;

    float acc[4][8][4];
#pragma unroll
    for (int i = 0; i < 4; i++)
#pragma unroll
        for (int j = 0; j < 8; j++)
#pragma unroll
            for (int r = 0; r < 4; r++) acc[i][j][r] = 0.f;

    // loader: 128 threads, A 128x32 + B 128x32 halves, 4+4 cp.async each
    auto load_chunk = [&](int buf, int kt) {
        __half* Asb = sm + buf * STAGE_H;
        __half* Bsb = Asb + TILE_H;
        const __half* Ag = A + (size_t)m0 * CTXD + kt * BK;
        const __half* Bg = B + (size_t)n0 * CTXD + kt * BK;
#pragma unroll
        for (int i = 0; i < 4; i++) {
            int idx = i * 128 + tid;
            int row = idx >> 2;
            int c8  = (idx & 3) * 8;
            cpasync16((uint32_t)__cvta_generic_to_shared(Asb + row * SSTRIDE + c8),
                      Ag + (size_t)row * CTXD + c8);
        }
#pragma unroll
        for (int i = 0; i < 4; i++) {
            int idx = i * 128 + tid;
            int row = idx >> 2;
            int c8  = (idx & 3) * 8;
            cpasync16((uint32_t)__cvta_generic_to_shared(Bsb + row * SSTRIDE + c8),
                      Bg + (size_t)row * CTXD + c8);
        }
        asm volatile("cp.async.commit_group;\n");
    };

    load_chunk(0, 0);
    load_chunk(1, 1);

    for (int kt = 0; kt < NT; ++kt) {
        if (kt + 2 < NT) {
            load_chunk((kt + 2) % 3, kt + 2);
            asm volatile("cp.async.wait_group 2;\n");
        } else if (kt + 1 < NT) {
            asm volatile("cp.async.wait_group 1;\n");
        } else {
            asm volatile("cp.async.wait_group 0;\n");
        }
        __syncthreads();

        const __half* Asb = sm + (kt % 3) * STAGE_H;
        const __half* Bsb = Asb + TILE_H;

#pragma unroll
        for (int ks = 0; ks < 2; ++ks) {
            const int k0 = ks * 16;

            uint32_t af[4][4];
#pragma unroll
            for (int mi = 0; mi < 4; ++mi) {
                const __half* p = Asb + (wm * 64 + mi * 16 + g) * SSTRIDE + k0 + t4 * 2;
                af[mi][0] = *reinterpret_cast<const uint32_t*>(p);
                af[mi][1] = *reinterpret_cast<const uint32_t*>(p + 8 * SSTRIDE);
                af[mi][2] = *reinterpret_cast<const uint32_t*>(p + 8);
                af[mi][3] = *reinterpret_cast<const uint32_t*>(p + 8 * SSTRIDE + 8);
            }
            uint32_t bf[8][2];
#pragma unroll
            for (int ni = 0; ni < 8; ++ni) {
                const __half* p = Bsb + (wn * 64 + ni * 8 + g) * SSTRIDE + k0 + t4 * 2;
                bf[ni][0] = *reinterpret_cast<const uint32_t*>(p);
                bf[ni][1] = *reinterpret_cast<const uint32_t*>(p + 8);
            }
#pragma unroll
            for (int mi = 0; mi < 4; ++mi)
#pragma unroll
                for (int ni = 0; ni < 8; ++ni) {
                    asm volatile(
                        "mma.sync.aligned.m16n8k16.row.col.f32.f16.f16.f32 "
                        "{%0,%1,%2,%3},{%4,%5,%6,%7},{%8,%9},{%0,%1,%2,%3};\n"
                        : "+f"(acc[mi][ni][0]), "+f"(acc[mi][ni][1]),
                          "+f"(acc[mi][ni][2]), "+f"(acc[mi][ni][3])
                        : "r"(af[mi][0]), "r"(af[mi][1]),
                          "r"(af[mi][2]), "r"(af[mi][3]),
                          "r"(bf[ni][0]), "r"(bf[ni][1]));
                }
        }
        __syncthreads();
    }

    // epilogue
#pragma unroll
    for (int mi = 0; mi < 4; ++mi) {
#pragma unroll
        for (int ni = 0; ni < 8; ++ni) {
            const int r = m0 + wm * 64 + mi * 16 + g;
            const int c = n0 + wn * 64 + ni * 8 + t4 * 2;
            float2 v0 = make_float2(acc[mi][ni][0], acc[mi][ni][1]);
            float2 v1 = make_float2(acc[mi][ni][2], acc[mi][ni][3]);
            *reinterpret_cast<float2*>(C + (size_t)r * HIDD + c)       = v0;
            *reinterpret_cast<float2*>(C + (size_t)(r + 8) * HIDD + c) = v1;
        }
    }
}

// ---------------------------------------------------------------------------
extern "C" void kernel_launch(void* const* d_in, const int* in_sizes, int n_in,
                              void* d_out, int out_size) {
    const float* x      = (const float*)d_in[0];
    const float* W      = (const float*)d_in[1];
    const int*   nn_idx = (const int*)  d_in[2];
    const float* sim    = (const float*)d_in[3];
    float*       out    = (float*)d_out;

    __half* aggh = nullptr;
    __half* wh   = nullptr;
    cudaGetSymbolAddress((void**)&aggh, g_aggh);
    cudaGetSymbolAddress((void**)&wh,   g_Wh);

    cudaFuncSetAttribute(gemm_hmma,
                         cudaFuncAttributeMaxDynamicSharedMemorySize, GEMM_SMEM);

    dim3 g1(NCELLS / 2, NBATCH);
    agg_kernel<<<g1, 128>>>(x, nn_idx, sim);

    dim3 gt(HIDD / 32, CTXD / 32);
    wtrans_kernel<<<gt, 256>>>(W, wh);

    dim3 g2(HIDD / BN, MTOT / BM);   // (16, 256)
    gemm_hmma<<<g2, 128, GEMM_SMEM>>>(aggh, wh, out);
}

// round 6
// speedup vs baseline: 5.1579x; 1.1205x over previous
#include <cuda_runtime.h>
#include <cuda_fp16.h>
#include <cstdint>

// Problem constants
#define CTXD   512
#define HIDD   2048
#define NCELLS 4096      // 64*64
#define NBATCH 8
#define KNN    8
#define MTOT   (NBATCH * NCELLS)   // 32768

// Scratch (allowed: __device__ globals)
__device__ __half g_aggh[(size_t)MTOT * CTXD];  // 32 MB fp16 agg
__device__ __half g_Wh[(size_t)HIDD * CTXD];    // 2 MB  fp16 W^T (N rows, K cols)

// ---------------------------------------------------------------------------
// Kernel 1: agg -> fp16, four cells per block for MLP
// ---------------------------------------------------------------------------
__global__ __launch_bounds__(128) void agg_kernel(
    const float* __restrict__ x,
    const int*   __restrict__ nn_idx,
    const float* __restrict__ sim)
{
    const int n0 = blockIdx.x * 4;     // cells n0..n0+3
    const int b  = blockIdx.y;
    const int t  = threadIdx.x;

    __shared__ int   s_idx[4 * KNN];
    __shared__ float s_sim[4 * KNN];
    if (t < 4 * KNN) {
        s_idx[t] = nn_idx[n0 * KNN + t];
        s_sim[t] = sim[n0 * KNN + t];
    }
    __syncthreads();

    const float4* xb = reinterpret_cast<const float4*>(x) +
                       (size_t)b * NCELLS * (CTXD / 4);
    uint2* dst = reinterpret_cast<uint2*>(g_aggh);

#pragma unroll
    for (int c = 0; c < 4; c++) {
        float4 acc = make_float4(0.f, 0.f, 0.f, 0.f);
#pragma unroll
        for (int k = 0; k < KNN; k++) {
            const float  s = s_sim[c * KNN + k];
            const float4 v = xb[(size_t)s_idx[c * KNN + k] * (CTXD / 4) + t];
            acc.x = fmaf(s, v.x, acc.x);
            acc.y = fmaf(s, v.y, acc.y);
            acc.z = fmaf(s, v.z, acc.z);
            acc.w = fmaf(s, v.w, acc.w);
        }
        __half2 h0 = __float22half2_rn(make_float2(acc.x, acc.y));
        __half2 h1 = __float22half2_rn(make_float2(acc.z, acc.w));
        uint2 p;
        p.x = *reinterpret_cast<uint32_t*>(&h0);
        p.y = *reinterpret_cast<uint32_t*>(&h1);
        dst[((size_t)b * NCELLS + n0 + c) * (CTXD / 4) + t] = p;
    }
}

// ---------------------------------------------------------------------------
// Kernel 1b: Wt[n][k] = (half)W[k][n]
// ---------------------------------------------------------------------------
__global__ __launch_bounds__(256) void wtrans_kernel(
    const float* __restrict__ W, __half* __restrict__ o)
{
    __shared__ float tile[32][33];
    const int bx = blockIdx.x;
    const int by = blockIdx.y;
    const int tx = threadIdx.x & 31;
    const int ty = threadIdx.x >> 5;
#pragma unroll
    for (int i = 0; i < 4; i++)
        tile[ty + i * 8][tx] = W[(size_t)(by * 32 + ty + i * 8) * HIDD + bx * 32 + tx];
    __syncthreads();
#pragma unroll
    for (int i = 0; i < 4; i++)
        o[(size_t)(bx * 32 + ty + i * 8) * CTXD + by * 32 + tx] =
            __float2half(tile[tx][ty + i * 8]);
}

// ---------------------------------------------------------------------------
// Kernel 2: fp16 mma.sync GEMM, 128x128 CTA tile, 4 warps (warp tile 64x64),
// BK=64, 3-stage cp.async, ldmatrix fragment loads, fp32 accum.
// ---------------------------------------------------------------------------
#define BM 128
#define BN 128
#define BK 64
#define NT (CTXD / BK)         // 8 k-chunks
#define SSTRIDE 72             // BK + 8 pad (halves) -> LDSM conflict-free
#define TILE_H (128 * SSTRIDE)
#define STAGE_H (2 * TILE_H)
#define GEMM_SMEM (3 * STAGE_H * 2)   // 110592 bytes

__device__ __forceinline__ void cpasync16(uint32_t saddr, const void* g) {
    asm volatile("cp.async.cg.shared.global [%0], [%1], 16;\n" :: "r"(saddr), "l"(g));
}
__device__ __forceinline__ void ldsm_x4(uint32_t& r0, uint32_t& r1,
                                        uint32_t& r2, uint32_t& r3, uint32_t a) {
    asm volatile("ldmatrix.sync.aligned.m8n8.x4.shared.b16 {%0,%1,%2,%3},[%4];"
                 : "=r"(r0), "=r"(r1), "=r"(r2), "=r"(r3) : "r"(a));
}

__global__ __launch_bounds__(128, 2) void gemm_hmma(
    const __half* __restrict__ A,   // [MTOT][CTXD]
    const __half* __restrict__ B,   // [HIDD][CTXD]  (W^T)
    float*        __restrict__ C)   // [MTOT][HIDD]
{
    extern __shared__ __half sm[];

    const int tid  = threadIdx.x;
    const int lane = tid & 31;
    const int warp = tid >> 5;      // 0..3
    const int wm   = warp & 1;      // 64-row M half
    const int wn   = warp >> 1;     // 64-col N half
    const int g    = lane >> 2;     // 0..7
    const int t4   = lane & 3;      // 0..3

    const int m0 = blockIdx.y * BM;
    const int n0 = blockIdx.x * BN;

    float acc[4][8][4];
#pragma unroll
    for (int i = 0; i < 4; i++)
#pragma unroll
        for (int j = 0; j < 8; j++)
#pragma unroll
            for (int r = 0; r < 4; r++) acc[i][j][r] = 0.f;

    // loader: chunk kt -> stage buf. A/B: 128 rows x 64 halves (8 x 16B rows)
    auto load_chunk = [&](int buf, int kt) {
        __half* Asb = sm + buf * STAGE_H;
        __half* Bsb = Asb + TILE_H;
        const __half* Ag = A + (size_t)m0 * CTXD + kt * BK;
        const __half* Bg = B + (size_t)n0 * CTXD + kt * BK;
#pragma unroll
        for (int i = 0; i < 8; i++) {
            int idx = i * 128 + tid;
            int row = idx >> 3;
            int c8  = (idx & 7) * 8;
            cpasync16((uint32_t)__cvta_generic_to_shared(Asb + row * SSTRIDE + c8),
                      Ag + (size_t)row * CTXD + c8);
        }
#pragma unroll
        for (int i = 0; i < 8; i++) {
            int idx = i * 128 + tid;
            int row = idx >> 3;
            int c8  = (idx & 7) * 8;
            cpasync16((uint32_t)__cvta_generic_to_shared(Bsb + row * SSTRIDE + c8),
                      Bg + (size_t)row * CTXD + c8);
        }
        asm volatile("cp.async.commit_group;\n");
    };

    load_chunk(0, 0);
    load_chunk(1, 1);

    // ldmatrix lane address components
    const int a_r  = lane & 15;          // row within 16
    const int a_k  = (lane >> 4) * 8;    // 0 or 8
    const int b_r  = lane & 7;           // row within 8
    const int b_no = ((lane >> 3) >> 1) * 8;  // 0 or 8 (ni sub-offset)
    const int b_ko = ((lane >> 3) & 1) * 8;   // 0 or 8 (k sub-offset)

    for (int kt = 0; kt < NT; ++kt) {
        if (kt + 1 < NT) asm volatile("cp.async.wait_group 1;\n");
        else             asm volatile("cp.async.wait_group 0;\n");
        __syncthreads();
        if (kt + 2 < NT) load_chunk((kt + 2) % 3, kt + 2);

        const __half* Asb = sm + (kt % 3) * STAGE_H;
        const __half* Bsb = Asb + TILE_H;

#pragma unroll
        for (int ks = 0; ks < 4; ++ks) {
            const int k0 = ks * 16;

            uint32_t af[4][4];
#pragma unroll
            for (int mi = 0; mi < 4; ++mi) {
                uint32_t a = (uint32_t)__cvta_generic_to_shared(
                    Asb + (wm * 64 + mi * 16 + a_r) * SSTRIDE + k0 + a_k);
                ldsm_x4(af[mi][0], af[mi][1], af[mi][2], af[mi][3], a);
            }
            uint32_t bf[8][2];
#pragma unroll
            for (int nj = 0; nj < 4; ++nj) {
                uint32_t a = (uint32_t)__cvta_generic_to_shared(
                    Bsb + (wn * 64 + nj * 16 + b_no + b_r) * SSTRIDE + k0 + b_ko);
                ldsm_x4(bf[2 * nj][0], bf[2 * nj][1],
                        bf[2 * nj + 1][0], bf[2 * nj + 1][1], a);
            }
#pragma unroll
            for (int mi = 0; mi < 4; ++mi)
#pragma unroll
                for (int ni = 0; ni < 8; ++ni) {
                    asm volatile(
                        "mma.sync.aligned.m16n8k16.row.col.f32.f16.f16.f32 "
                        "{%0,%1,%2,%3},{%4,%5,%6,%7},{%8,%9},{%0,%1,%2,%3};\n"
                        : "+f"(acc[mi][ni][0]), "+f"(acc[mi][ni][1]),
                          "+f"(acc[mi][ni][2]), "+f"(acc[mi][ni][3])
                        : "r"(af[mi][0]), "r"(af[mi][1]),
                          "r"(af[mi][2]), "r"(af[mi][3]),
                          "r"(bf[ni][0]), "r"(bf[ni][1]));
                }
        }
        __syncthreads();
    }

    // epilogue
#pragma unroll
    for (int mi = 0; mi < 4; ++mi) {
#pragma unroll
        for (int ni = 0; ni < 8; ++ni) {
            const int r = m0 + wm * 64 + mi * 16 + g;
            const int c = n0 + wn * 64 + ni * 8 + t4 * 2;
            float2 v0 = make_float2(acc[mi][ni][0], acc[mi][ni][1]);
            float2 v1 = make_float2(acc[mi][ni][2], acc[mi][ni][3]);
            *reinterpret_cast<float2*>(C + (size_t)r * HIDD + c)       = v0;
            *reinterpret_cast<float2*>(C + (size_t)(r + 8) * HIDD + c) = v1;
        }
    }
}

// ---------------------------------------------------------------------------
extern "C" void kernel_launch(void* const* d_in, const int* in_sizes, int n_in,
                              void* d_out, int out_size) {
    const float* x      = (const float*)d_in[0];
    const float* W      = (const float*)d_in[1];
    const int*   nn_idx = (const int*)  d_in[2];
    const float* sim    = (const float*)d_in[3];
    float*       out    = (float*)d_out;

    __half* aggh = nullptr;
    __half* wh   = nullptr;
    cudaGetSymbolAddress((void**)&aggh, g_aggh);
    cudaGetSymbolAddress((void**)&wh,   g_Wh);

    cudaFuncSetAttribute(gemm_hmma,
                         cudaFuncAttributeMaxDynamicSharedMemorySize, GEMM_SMEM);

    dim3 gt(HIDD / 32, CTXD / 32);
    wtrans_kernel<<<gt, 256>>>(W, wh);

    dim3 g1(NCELLS / 4, NBATCH);
    agg_kernel<<<g1, 128>>>(x, nn_idx, sim);

    dim3 g2(HIDD / BN, MTOT / BM);   // (16, 256)
    gemm_hmma<<<g2, 128, GEMM_SMEM>>>(aggh, wh, out);
}